// round 5
// baseline (speedup 1.0000x reference)
#include <cuda_runtime.h>
#include <cuda_bf16.h>
#include <math.h>

#define BB    2304
#define CH    22
#define TP    250
#define ST    64
#define KW    13
#define RR    32
#define NFE   528

typedef unsigned long long ull;

__device__ float g_z[(size_t)BB * ST * TP];
__device__ float g_y[(size_t)BB * RR * RR];

__device__ __forceinline__ ull pk2(float a, float b) {
    ull r;
    asm("mov.b64 %0, {%1, %2};" : "=l"(r)
        : "r"(__float_as_uint(a)), "r"(__float_as_uint(b)));
    return r;
}
__device__ __forceinline__ void upk2(ull v, float &a, float &b) {
    unsigned int lo, hi;
    asm("mov.b64 {%0, %1}, %2;" : "=r"(lo), "=r"(hi) : "l"(v));
    a = __uint_as_float(lo); b = __uint_as_float(hi);
}
__device__ __forceinline__ void fma2(ull &d, ull a, ull b) {
    asm("fma.rn.f32x2 %0, %1, %2, %0;" : "+l"(d) : "l"(a), "l"(b));
}

// ============================================================
// K1: pool(4) + conv(22x13,pad6) + BN -> g_z[b][o][t]
// block = one b. 256 threads = 8 warps.
// warp w covers o in [w*8, w*8+8): lane = (ln 0..15, osub 0..1),
// thread computes 4 o x 16 t. All inner ops are LDS.64 / FFMA2.
// smem: w2 (64x286 packed ull) + xs (22x16 windows of 27 ull)
// ============================================================
#define W2_ULL   (ST * 286)          // 18304 ull = 146432 B
#define XS_ULL   (CH * 16 * 27)      // 9504 ull  =  76032 B
#define CONV_SMEM ((W2_ULL + XS_ULL) * 8)   // 222464 B

__global__ void __launch_bounds__(256, 1)
k_conv(const float* __restrict__ x, const float* __restrict__ cw,
       const float* __restrict__ cb, const float* __restrict__ bg,
       const float* __restrict__ bbv, const float* __restrict__ bm,
       const float* __restrict__ bv)
{
    extern __shared__ ull dsm[];
    ull* w2 = dsm;
    ull* xs = dsm + W2_ULL;
    float* xpf = (float*)dsm;            // temp pooled input, 22 x 272 (lives in w2 area)
    __shared__ float sc[64], sh[64];

    int b = blockIdx.x, tid = threadIdx.x;

    // phase 1: zero-pad + pool(4)
    for (int i = tid; i < CH * 272; i += 256) xpf[i] = 0.f;
    __syncthreads();
    const float4* xb = (const float4*)(x + (size_t)b * CH * 1000);
    for (int i = tid; i < CH * TP; i += 256) {
        int c = i / TP, t = i - c * TP;
        float4 v = xb[i];
        xpf[c * 272 + 6 + t] = 0.25f * (v.x + v.y + v.z + v.w);
    }
    __syncthreads();

    // phase 2: build pre-paired windows.
    // unit (c, ln): covers outputs t0=16*ln .. t0+15, window x[t0-6 .. t0+21]
    //   p in [0,14):  xe_p = (pool[t0-6+2p], pool[t0-6+2p+1])
    //   p in [14,27): xo_q = (pool[t0-5+2q], pool[t0-4+2q]), q=p-14
    for (int s = tid; s < XS_ULL; s += 256) {
        int unit = s / 27, p = s - unit * 27;
        int c = unit >> 4, ln = unit & 15;
        int base = c * 272 + ln * 16;       // == xp index of t0-6 (+6 pad)
        int idx = (p < 14) ? (base + 2 * p) : (base + 1 + 2 * (p - 14));
        xs[s] = pk2(xpf[idx], xpf[idx + 1]);
    }
    __syncthreads();

    // phase 3: packed weights overwrite xpf area; BN constants
    for (int i = tid; i < W2_ULL; i += 256) {
        float wv = cw[i];
        w2[i] = pk2(wv, wv);
    }
    if (tid < 64) {
        float inv = bg[tid] * rsqrtf(bv[tid] + 1e-5f);
        sc[tid] = inv;
        sh[tid] = cb[tid] * inv + bbv[tid] - bm[tid] * inv;
    }
    __syncthreads();

    // phase 4: compute
    int lane = tid & 31, warp = tid >> 5;
    int ln = lane & 15, osub = lane >> 4;
    int obase = warp * 8 + osub * 4;
    int t0 = ln * 16;

    ull acc[4][8];
    #pragma unroll
    for (int o = 0; o < 4; ++o)
        #pragma unroll
        for (int u = 0; u < 8; ++u) acc[o][u] = 0ull;

    #pragma unroll 1
    for (int c = 0; c < CH; ++c) {
        const ull* xr = xs + (c * 16 + ln) * 27;
        ull xe[14], xo[13];
        #pragma unroll
        for (int p = 0; p < 14; ++p) xe[p] = xr[p];
        #pragma unroll
        for (int p = 0; p < 13; ++p) xo[p] = xr[14 + p];

        #pragma unroll
        for (int o = 0; o < 4; ++o) {
            const ull* wr = w2 + (obase + o) * 286 + c * 13;
            #pragma unroll
            for (int k = 0; k < 13; ++k) {
                ull wv = wr[k];
                int m = k >> 1;
                if ((k & 1) == 0) {
                    #pragma unroll
                    for (int u = 0; u < 8; ++u) fma2(acc[o][u], xe[m + u], wv);
                } else {
                    #pragma unroll
                    for (int u = 0; u < 8; ++u) fma2(acc[o][u], xo[m + u], wv);
                }
            }
        }
    }

    // epilogue: BN + store
    #pragma unroll
    for (int o = 0; o < 4; ++o) {
        float scl = sc[obase + o], shf = sh[obase + o];
        float* zr = g_z + ((size_t)b * ST + obase + o) * TP + t0;
        #pragma unroll
        for (int u = 0; u < 8; ++u) {
            float lo, hi; upk2(acc[o][u], lo, hi);
            int t = t0 + 2 * u;
            if (t < TP)     zr[2 * u]     = lo * scl + shf;
            if (t + 1 < TP) zr[2 * u + 1] = hi * scl + shf;
        }
    }
}

// ============================================================
// K2: per b: 3 blocks -> center, P = W*Zc, y += P P^T / tr
//     y = y/3 + 1e-5 * W W^T  -> g_y
// ============================================================
__global__ void __launch_bounds__(256)
k_covmap(const float* __restrict__ W)
{
    __shared__ float zs[64 * 85];
    __shared__ float ps[32 * 85];
    __shared__ float Wsh[32 * 64];
    __shared__ float yacc[1024];
    __shared__ float red[256];
    __shared__ float smean[64];
    __shared__ float s_rtr;

    int b = blockIdx.x, tid = threadIdx.x;
    int ri = tid >> 3, j0 = (tid & 7) * 4;   // each thread owns yacc[ri][j0..j0+3]

    for (int i = tid; i < 2048; i += 256) Wsh[i] = W[i];
    for (int i = tid; i < 1024; i += 256) yacc[i] = 0.f;
    __syncthreads();

    const int offs[3] = {0, 84, 167};
    const int lens[3] = {84, 83, 83};

    for (int blk = 0; blk < 3; ++blk) {
        int off = offs[blk], l = lens[blk];
        for (int i = tid; i < 64 * l; i += 256) {
            int c = i / l, t = i - c * l;
            zs[c * 85 + t] = g_z[((size_t)b * 64 + c) * TP + off + t];
        }
        __syncthreads();
        if (tid < 64) {
            float s = 0.f;
            for (int t = 0; t < l; ++t) s += zs[tid * 85 + t];
            smean[tid] = s / (float)l;
        }
        __syncthreads();
        float loc = 0.f;
        for (int i = tid; i < 64 * l; i += 256) {
            int c = i / l, t = i - c * l;
            float v = zs[c * 85 + t] - smean[c];
            zs[c * 85 + t] = v;
            loc += v * v;
        }
        red[tid] = loc; __syncthreads();
        for (int s = 128; s > 0; s >>= 1) {
            if (tid < s) red[tid] += red[tid + s];
            __syncthreads();
        }
        if (tid == 0) s_rtr = 1.f / red[0];
        __syncthreads();

        // P(32 x l) = Wsh(32x64) * zs(64 x l)
        {
            int ty = tid >> 4, tx = tid & 15;
            int o0 = 2 * ty;
            float a0[6] = {0,0,0,0,0,0}, a1[6] = {0,0,0,0,0,0};
            for (int c = 0; c < 64; ++c) {
                float w0 = Wsh[o0 * 64 + c];
                float w1 = Wsh[(o0 + 1) * 64 + c];
                const float* zr = zs + c * 85 + tx;
                #pragma unroll
                for (int j = 0; j < 6; ++j) {
                    int t = tx + 16 * j;
                    if (t < l) {
                        float zv = zr[16 * j];
                        a0[j] += w0 * zv;
                        a1[j] += w1 * zv;
                    }
                }
            }
            #pragma unroll
            for (int j = 0; j < 6; ++j) {
                int t = tx + 16 * j;
                if (t < l) {
                    ps[o0 * 85 + t] = a0[j];
                    ps[(o0 + 1) * 85 + t] = a1[j];
                }
            }
        }
        __syncthreads();

        // yacc += rtr * P P^T  (all 256 threads: 4 entries each)
        {
            float a0 = 0.f, a1 = 0.f, a2 = 0.f, a3 = 0.f;
            const float* pu = ps + ri * 85;
            const float* pv = ps + j0 * 85;
            for (int t = 0; t < l; ++t) {
                float u = pu[t];
                a0 += u * pv[t];
                a1 += u * pv[85 + t];
                a2 += u * pv[170 + t];
                a3 += u * pv[255 + t];
            }
            float rtr = s_rtr;
            yacc[ri * 32 + j0]     += a0 * rtr;
            yacc[ri * 32 + j0 + 1] += a1 * rtr;
            yacc[ri * 32 + j0 + 2] += a2 * rtr;
            yacc[ri * 32 + j0 + 3] += a3 * rtr;
        }
        __syncthreads();
    }

    // y = yacc/3 + 1e-5 * W W^T
    {
        float a0 = 0.f, a1 = 0.f, a2 = 0.f, a3 = 0.f;
        const float* wu = Wsh + ri * 64;
        const float* wv = Wsh + j0 * 64;
        for (int c = 0; c < 64; ++c) {
            float u = wu[c];
            a0 += u * wv[c];
            a1 += u * wv[64 + c];
            a2 += u * wv[128 + c];
            a3 += u * wv[192 + c];
        }
        float* yr = g_y + (size_t)b * 1024 + ri * 32 + j0;
        yr[0] = yacc[ri * 32 + j0]     * (1.f / 3.f) + 1e-5f * a0;
        yr[1] = yacc[ri * 32 + j0 + 1] * (1.f / 3.f) + 1e-5f * a1;
        yr[2] = yacc[ri * 32 + j0 + 2] * (1.f / 3.f) + 1e-5f * a2;
        yr[3] = yacc[ri * 32 + j0 + 3] * (1.f / 3.f) + 1e-5f * a3;
    }
}

// ============================================================
// K3: one warp per 32x32 SPD matrix: Hestenes Jacobi eigh,
//     logm = U log(max(lam,1e-4)) U^T, write scaled triu -> fe
// ============================================================
__global__ void __launch_bounds__(256)
k_eig(float* __restrict__ feout)
{
    __shared__ float sm[8 * 1088];

    int tid = threadIdx.x;
    int wid = tid >> 5, lane = tid & 31;
    int b = blockIdx.x * 8 + wid;
    if (b >= BB) return;

    const float* Y = g_y + (size_t)b * 1024;
    float a[32];
    #pragma unroll
    for (int i = 0; i < 32; ++i) a[i] = Y[i * 32 + lane];

    for (int sweep = 0; sweep < 8; ++sweep) {
        for (int r = 0; r < 31; ++r) {
            int partner;
            if (lane == 0) partner = (30 + r) % 31 + 1;
            else {
                int pos = ((lane - 1 - r) % 31 + 31) % 31 + 1;
                int pp = 31 - pos;
                partner = (pp == 0) ? 0 : ((pp - 1 + r) % 31) + 1;
            }
            float oth[32];
            #pragma unroll
            for (int i = 0; i < 32; ++i)
                oth[i] = __shfl_sync(0xffffffffu, a[i], partner);
            float own = 0.f, dot = 0.f;
            #pragma unroll
            for (int i = 0; i < 32; ++i) { own += a[i] * a[i]; dot += a[i] * oth[i]; }
            float othn = __shfl_sync(0xffffffffu, own, partner);
            bool isp = lane < partner;
            float app = isp ? own : othn;
            float aqq = isp ? othn : own;
            float c = 1.f, s = 0.f;
            if (dot * dot > 1e-24f * app * aqq) {
                float zeta = (aqq - app) / (2.f * dot);
                float t = ((zeta >= 0.f) ? 1.f : -1.f) /
                          (fabsf(zeta) + sqrtf(1.f + zeta * zeta));
                c = rsqrtf(1.f + t * t);
                s = c * t;
            }
            #pragma unroll
            for (int i = 0; i < 32; ++i)
                a[i] = isp ? (c * a[i] - s * oth[i]) : (s * oth[i] + c * a[i]);
        }
    }

    float own = 0.f;
    #pragma unroll
    for (int i = 0; i < 32; ++i) own += a[i] * a[i];
    float lam = sqrtf(own);
    float g = logf(fmaxf(lam, 1e-4f));
    float inv = 1.f / lam;

    float* Us = sm + wid * 1088;
    float* gs = Us + 1056;
    #pragma unroll
    for (int i = 0; i < 32; ++i) Us[lane * 33 + i] = a[i] * inv;
    gs[lane] = g;
    __syncwarp();

    float scal[32];
    #pragma unroll
    for (int j = 0; j < 32; ++j) scal[j] = gs[j] * Us[j * 33 + lane];
    float acc[32];
    #pragma unroll
    for (int i = 0; i < 32; ++i) acc[i] = 0.f;
    #pragma unroll
    for (int j = 0; j < 32; ++j) {
        float sj = scal[j];
        #pragma unroll
        for (int i = 0; i < 32; ++i) acc[i] += sj * Us[j * 33 + i];
    }

    const float SQ2 = 1.41421356237309515f;
    int bi = 32 * lane - (lane * (lane - 1)) / 2 - lane;
    float* fb = feout + (size_t)b * NFE + bi;
    #pragma unroll
    for (int j = 0; j < 32; ++j) {
        if (j >= lane) fb[j] = acc[j] * ((j == lane) ? 1.f : SQ2);
    }
}

// ============================================================
// K4: logits(256,4) = fe(256,4752) @ Wl(4,4752)^T + bl
// ============================================================
__global__ void __launch_bounds__(128)
k_linear(const float* __restrict__ fe, const float* __restrict__ Wl,
         const float* __restrict__ bl, float* __restrict__ out)
{
    __shared__ float red[128 * 4];
    int bs = blockIdx.x, tid = threadIdx.x;
    const float* fr = fe + (size_t)bs * 4752;
    float acc[4] = {0.f, 0.f, 0.f, 0.f};
    for (int i = tid; i < 4752; i += 128) {
        float v = fr[i];
        #pragma unroll
        for (int c = 0; c < 4; ++c) acc[c] += v * Wl[c * 4752 + i];
    }
    #pragma unroll
    for (int c = 0; c < 4; ++c) red[tid * 4 + c] = acc[c];
    __syncthreads();
    for (int s = 64; s > 0; s >>= 1) {
        if (tid < s) {
            #pragma unroll
            for (int c = 0; c < 4; ++c) red[tid * 4 + c] += red[(tid + s) * 4 + c];
        }
        __syncthreads();
    }
    if (tid < 4) out[bs * 4 + tid] = red[tid] + bl[tid];
}

extern "C" void kernel_launch(void* const* d_in, const int* in_sizes, int n_in,
                              void* d_out, int out_size) {
    const float* x   = (const float*)d_in[0];
    const float* cw  = (const float*)d_in[1];
    const float* cb  = (const float*)d_in[2];
    const float* bg  = (const float*)d_in[3];
    const float* bb  = (const float*)d_in[4];
    const float* bm  = (const float*)d_in[5];
    const float* bv  = (const float*)d_in[6];
    const float* W   = (const float*)d_in[7];
    const float* Wl  = (const float*)d_in[8];
    const float* bl  = (const float*)d_in[9];
    float* fe     = (float*)d_out;
    float* logits = fe + (size_t)BB * NFE;

    static int smem_set = 0;
    if (!smem_set) {
        cudaFuncSetAttribute(k_conv, cudaFuncAttributeMaxDynamicSharedMemorySize,
                             CONV_SMEM);
        smem_set = 1;
    }

    k_conv<<<BB, 256, CONV_SMEM>>>(x, cw, cb, bg, bb, bm, bv);
    k_covmap<<<BB, 256>>>(W);
    k_eig<<<BB / 8, 256>>>(fe);
    k_linear<<<256, 128>>>(fe, Wl, bl, logits);
}